// round 14
// baseline (speedup 1.0000x reference)
#include <cuda_runtime.h>
#include <math.h>

#define KDT   0.1f
#define KG    9.81f
#define KRHO  1028.0f

typedef unsigned long long u64;

// Constant layout (floats). All 6x6 matrices COLUMN-MAJOR:
// c[base + j*6 + i] = M[i][j]  -> 64-bit pair loads of (M[2p][j], M[2p+1][j]).
// [0:36)    Minv
// [36:72)   mTot
// [72:108)  MiLD = Minv @ linDamp
// [108:144) linDampFow
// [144:150) quadDamp diagonal
// [150:168) negGm (6x3): -Minv@Ag, column-major
// [168]     lf-nonzero flag
#define NC 172
__constant__ __align__(16) float c_consts[NC];

// Parallel prep: 64 threads, one-element-per-thread Gauss-Jordan in shared.
// Writes derived constants DIRECTLY into the constant-bank backing store.
// Fires the PDL trigger at entry so the main kernel can begin its staging
// phase concurrently; the main kernel's cudaGridDependencySynchronize()
// (placed before any constant read) waits for this grid's completion.
__global__ void prep_kernel(float* __restrict__ c_dst,
                            const float* mass, const float* volume,
                            const float* cog, const float* cob,
                            const float* mTot, const float* linDamp,
                            const float* linDampFow, const float* quadDamp) {
#if __CUDA_ARCH__ >= 900
    cudaTriggerProgrammaticLaunchCompletion();
#endif
    __shared__ float As[36], Bs[36], MiLD[36], Ag[18], fv[6];
    __shared__ int piv_s;

    const int t = threadIdx.x;
    const int r = t / 6, c = t % 6;   // element (r,c) for t < 36

    if (t < 36) { As[t] = mTot[t]; Bs[t] = (r == c) ? 1.0f : 0.0f; }
    __syncthreads();

    // Gauss-Jordan with partial pivoting, 6 iterations
    for (int k = 0; k < 6; k++) {
        if (t == 0) {
            int piv = k; float best = fabsf(As[k * 6 + k]);
            for (int rr = k + 1; rr < 6; rr++) {
                float a = fabsf(As[rr * 6 + k]);
                if (a > best) { best = a; piv = rr; }
            }
            piv_s = piv;
        }
        __syncthreads();
        const int piv = piv_s;
        if (piv != k && t < 6) {
            float tmp = As[k * 6 + t]; As[k * 6 + t] = As[piv * 6 + t]; As[piv * 6 + t] = tmp;
            tmp = Bs[k * 6 + t]; Bs[k * 6 + t] = Bs[piv * 6 + t]; Bs[piv * 6 + t] = tmp;
        }
        __syncthreads();
        const float inv = 1.0f / As[k * 6 + k];   // broadcast read
        if (t < 6) { As[k * 6 + t] *= inv; Bs[k * 6 + t] *= inv; }
        __syncthreads();
        if (t < 6) fv[t] = As[t * 6 + k];         // per-row factors
        __syncthreads();
        if (t < 36 && r != k) {
            const float f = fv[r];
            As[t] -= f * As[k * 6 + c];
            Bs[t] -= f * Bs[k * 6 + c];
        }
        __syncthreads();
    }
    // Bs = Minv (row-major)

    // MiLD = Minv @ linDamp (one element per thread)
    if (t < 36) {
        float acc = 0.0f;
        for (int kk = 0; kk < 6; kk++) acc += Bs[r * 6 + kk] * linDamp[kk * 6 + c];
        MiLD[t] = acc;
    }

    // Restoring matrix Ag (thread 0; trivial)
    if (t == 0) {
        const float fgz = -mass[0] * KG;
        const float fbz = volume[0] * KRHO * KG;
        for (int ii = 0; ii < 18; ii++) Ag[ii] = 0.0f;
        Ag[0 * 3 + 0] = Ag[1 * 3 + 1] = Ag[2 * 3 + 2] = -(fgz + fbz);
        const float cg0 = cog[0], cg1 = cog[1], cg2 = cog[2];
        const float cb0 = cob[0], cb1 = cob[1], cb2 = cob[2];
        Ag[3 * 3 + 1] = -(-fgz * cg2 - fbz * cb2);
        Ag[3 * 3 + 2] = -( fgz * cg1 + fbz * cb1);
        Ag[4 * 3 + 0] = -( fgz * cg2 + fbz * cb2);
        Ag[4 * 3 + 2] = -(-fgz * cg0 - fbz * cb0);
        Ag[5 * 3 + 0] = -(-fgz * cg1 - fbz * cb1);
        Ag[5 * 3 + 1] = -( fgz * cg0 + fbz * cb0);
    }
    __syncthreads();

    // Column-major stores: c[base + j*6 + i] = M[i][j]; thread t<36 -> (j=t/6, i=t%6)
    if (t < 36) {
        const int j = t / 6, i = t % 6;
        c_dst[0   + t] = Bs[i * 6 + j];
        c_dst[36  + t] = mTot[i * 6 + j];
        c_dst[72  + t] = MiLD[i * 6 + j];
        c_dst[108 + t] = linDampFow[i * 6 + j];
    }
    if (t < 6) c_dst[144 + t] = quadDamp[t * 7];
    // negGm column-major: c[150 + jj*6 + i] = -(Minv@Ag)[i][jj]
    if (t < 18) {
        const int jj = t / 6, i = t % 6;
        float acc = 0.0f;
        for (int kk = 0; kk < 6; kk++) acc += Bs[i * 6 + kk] * Ag[kk * 3 + jj];
        c_dst[150 + jj * 6 + i] = -acc;
    }
    if (t == 32) {
        float nz = 0.0f;
        for (int ii = 0; ii < 36; ii++)
            if (linDampFow[ii] != 0.0f) nz = 1.0f;
        c_dst[168] = nz;
    }
}

// ---------------- packed f32x2 helpers ----------------
__device__ __forceinline__ u64 pk2(float lo, float hi) {
    u64 r; asm("mov.b64 %0,{%1,%2};" : "=l"(r) : "f"(lo), "f"(hi)); return r;
}
__device__ __forceinline__ u64 splat2(float a) {
    u64 r; asm("mov.b64 %0,{%1,%1};" : "=l"(r) : "f"(a)); return r;
}
__device__ __forceinline__ void unpk2(u64 p, float& lo, float& hi) {
    asm("mov.b64 {%0,%1},%2;" : "=f"(lo), "=f"(hi) : "l"(p));
}
__device__ __forceinline__ u64 f2fma(u64 a, u64 b, u64 c) {
    u64 d; asm("fma.rn.f32x2 %0,%1,%2,%3;" : "=l"(d) : "l"(a), "l"(b), "l"(c)); return d;
}
__device__ __forceinline__ u64 f2mul(u64 a, u64 b) {
    u64 d; asm("mul.rn.f32x2 %0,%1,%2;" : "=l"(d) : "l"(a), "l"(b)); return d;
}
__device__ __forceinline__ u64 f2add(u64 a, u64 b) {
    u64 d; asm("add.rn.f32x2 %0,%1,%2;" : "=l"(d) : "l"(a), "l"(b)); return d;
}
// 64-bit constant-bank fetch of a column pair (uniform address -> LDCU/UR path)
#define C2(base, j, p) (*reinterpret_cast<const u64*>(&c_consts[(base) + (j) * 6 + (p) * 2]))

// One RK stage. q,v scalar; sv = splats of v; Uvp = packed Minv@u.
__device__ __forceinline__ void fossen_stage(const float q[4], const float v[6],
                                             const u64 sv[6], const u64 Uvp[3],
                                             float pd[7], u64 vdp[3]) {
    const float qx = q[0], qy = q[1], qz = q[2], qw = q[3];

    const float r00 = 1.0f - 2.0f * (qy * qy + qz * qz);
    const float r01 = 2.0f * (qx * qy - qz * qw);
    const float r02 = 2.0f * (qx * qz + qy * qw);
    const float r10 = 2.0f * (qx * qy + qz * qw);
    const float r11 = 1.0f - 2.0f * (qx * qx + qz * qz);
    const float r12 = 2.0f * (qy * qz - qx * qw);
    const float r20 = 2.0f * (qx * qz - qy * qw);
    const float r21 = 2.0f * (qy * qz + qx * qw);
    const float r22 = 1.0f - 2.0f * (qx * qx + qy * qy);

    const float v0 = v[0], v1 = v[1], v2 = v[2];
    const float w0 = v[3], w1 = v[4], w2 = v[5];

    pd[0] = r00 * v0 + r01 * v1 + r02 * v2;
    pd[1] = r10 * v0 + r11 * v1 + r12 * v2;
    pd[2] = r20 * v0 + r21 * v1 + r22 * v2;
    pd[3] = 0.5f * (-qx * w0 - qy * w1 - qz * w2);
    pd[4] = 0.5f * ( qw * w0 - qz * w1 + qy * w2);
    pd[5] = 0.5f * ( qz * w0 + qw * w1 - qx * w2);
    pd[6] = 0.5f * (-qy * w0 + qx * w1 + qw * w2);

    // mv = mTot @ v  (packed, column-major accumulate)
    u64 mvp[3];
#pragma unroll
    for (int p = 0; p < 3; p++) mvp[p] = f2mul(C2(36, 0, p), sv[0]);
#pragma unroll
    for (int j = 1; j < 6; j++)
#pragma unroll
        for (int p = 0; p < 3; p++) mvp[p] = f2fma(C2(36, j, p), sv[j], mvp[p]);
    float mv0, mv1, mv2, mv3, mv4, mv5;
    unpk2(mvp[0], mv0, mv1); unpk2(mvp[1], mv2, mv3); unpk2(mvp[2], mv4, mv5);

    // s = quad|v|v - Cv  (scalar)
    float s[6];
    s[0] = c_consts[144] * fabsf(v0) * v0 + (mv1 * w2 - mv2 * w1);
    s[1] = c_consts[145] * fabsf(v1) * v1 + (mv2 * w0 - mv0 * w2);
    s[2] = c_consts[146] * fabsf(v2) * v2 + (mv0 * w1 - mv1 * w0);
    s[3] = c_consts[147] * fabsf(w0) * w0 + (mv1 * v2 - mv2 * v1) + (mv4 * w2 - mv5 * w1);
    s[4] = c_consts[148] * fabsf(w1) * w1 + (mv2 * v0 - mv0 * v2) + (mv5 * w0 - mv3 * w2);
    s[5] = c_consts[149] * fabsf(w2) * w2 + (mv0 * v1 - mv1 * v0) + (mv3 * w1 - mv4 * w0);

    // optional linDampFow term: s_i += v_i * (lf_i . v)
    if (c_consts[168] != 0.0f) {
        u64 dp[3];
#pragma unroll
        for (int p = 0; p < 3; p++) dp[p] = f2mul(C2(108, 0, p), sv[0]);
#pragma unroll
        for (int j = 1; j < 6; j++)
#pragma unroll
            for (int p = 0; p < 3; p++) dp[p] = f2fma(C2(108, j, p), sv[j], dp[p]);
        float d0, d1, d2, d3, d4, d5;
        unpk2(dp[0], d0, d1); unpk2(dp[1], d2, d3); unpk2(dp[2], d4, d5);
        s[0] += v0 * d0; s[1] += v1 * d1; s[2] += v2 * d2;
        s[3] += w0 * d3; s[4] += w1 * d4; s[5] += w2 * d5;
    }

    // vd = Uv + MiLD@v + Minv@s + negGm@r2   (packed)
    u64 acc[3] = { Uvp[0], Uvp[1], Uvp[2] };
#pragma unroll
    for (int j = 0; j < 6; j++) {
#pragma unroll
        for (int p = 0; p < 3; p++) acc[p] = f2fma(C2(72, j, p), sv[j], acc[p]);
    }
#pragma unroll
    for (int j = 0; j < 6; j++) {
        const u64 ssj = splat2(s[j]);
#pragma unroll
        for (int p = 0; p < 3; p++) acc[p] = f2fma(C2(0, j, p), ssj, acc[p]);
    }
    const u64 sr0 = splat2(r20), sr1 = splat2(r21), sr2 = splat2(r22);
#pragma unroll
    for (int p = 0; p < 3; p++) {
        acc[p] = f2fma(C2(150, 0, p), sr0, acc[p]);
        acc[p] = f2fma(C2(150, 1, p), sr1, acc[p]);
        acc[p] = f2fma(C2(150, 2, p), sr2, acc[p]);
    }
    vdp[0] = acc[0]; vdp[1] = acc[1]; vdp[2] = acc[2];
}

__global__ __launch_bounds__(256) void auv_kernel(const float* __restrict__ x,
                                                  const float* __restrict__ u,
                                                  float* __restrict__ out, int K) {
    __shared__ float sx[256 * 13];
    __shared__ float su[256 * 6];

    const int tid = threadIdx.x;
    const int rbase = blockIdx.x * 256;
    const int total_x = K * 13;
    const int total_u = K * 6;
    const int remx = total_x - rbase * 13;
    const int remu = total_u - rbase * 6;

    // ---- Staging phase: NO constant accesses (runs concurrently with prep) ----
    if (remx >= 256 * 13 && remu >= 256 * 6) {
        const float4* x4 = (const float4*)(x + (size_t)rbase * 13);
        float4* sx4 = (float4*)sx;
#pragma unroll
        for (int i = tid; i < 256 * 13 / 4; i += 256) sx4[i] = x4[i];
        const float4* u4 = (const float4*)(u + (size_t)rbase * 6);
        float4* su4 = (float4*)su;
#pragma unroll
        for (int i = tid; i < 256 * 6 / 4; i += 256) su4[i] = u4[i];
    } else {
        for (int i = tid; i < 256 * 13; i += 256)
            sx[i] = (i < remx) ? x[rbase * 13 + i] : 0.0f;
        for (int i = tid; i < 256 * 6; i += 256)
            su[i] = (i < remu) ? u[rbase * 6 + i] : 0.0f;
    }
    __syncthreads();

    // ---- Wait for prep_kernel's constant-bank writes before first LDCU ----
#if __CUDA_ARCH__ >= 900
    cudaGridDependencySynchronize();
#endif

    const int row = rbase + tid;
    const bool active = (row < K);

    float q[4], v[6];
    const float* mx = &sx[tid * 13];
#pragma unroll
    for (int i = 0; i < 4; i++) q[i] = mx[3 + i];
#pragma unroll
    for (int i = 0; i < 6; i++) v[i] = mx[7 + i];

    // Uv = Minv @ u (u constant across both RK stages)
    u64 Uvp[3];
    {
        const float* uu = &su[tid * 6];
        u64 s0 = splat2(uu[0]);
#pragma unroll
        for (int p = 0; p < 3; p++) Uvp[p] = f2mul(C2(0, 0, p), s0);
#pragma unroll
        for (int j = 1; j < 6; j++) {
            const u64 sj = splat2(uu[j]);
#pragma unroll
            for (int p = 0; p < 3; p++) Uvp[p] = f2fma(C2(0, j, p), sj, Uvp[p]);
        }
    }

    // Stage 1
    u64 sv1[6];
#pragma unroll
    for (int j = 0; j < 6; j++) sv1[j] = splat2(v[j]);
    float pd1[7]; u64 vd1p[3];
    fossen_stage(q, v, sv1, Uvp, pd1, vd1p);

    // Midpoint state
    const u64 dt2 = splat2(KDT);
    u64 vp[3] = { pk2(v[0], v[1]), pk2(v[2], v[3]), pk2(v[4], v[5]) };
    float q2[4], v2[6];
#pragma unroll
    for (int i = 0; i < 4; i++) q2[i] = q[i] + KDT * pd1[3 + i];
    {
        u64 v2p[3];
#pragma unroll
        for (int p = 0; p < 3; p++) v2p[p] = f2fma(dt2, vd1p[p], vp[p]);
        unpk2(v2p[0], v2[0], v2[1]); unpk2(v2p[1], v2[2], v2[3]); unpk2(v2p[2], v2[4], v2[5]);
    }

    // Stage 2
    u64 sv2[6];
#pragma unroll
    for (int j = 0; j < 6; j++) sv2[j] = splat2(v2[j]);
    float pd2[7]; u64 vd2p[3];
    fossen_stage(q2, v2, sv2, Uvp, pd2, vd2p);

    // Combine (RK2) + quaternion normalize
    const float hdt = 0.5f * KDT;
    float res[13];
#pragma unroll
    for (int i = 0; i < 3; i++) res[i] = mx[i] + hdt * (pd1[i] + pd2[i]);
    float qo[4];
#pragma unroll
    for (int i = 0; i < 4; i++) qo[i] = q[i] + hdt * (pd1[3 + i] + pd2[3 + i]);
    const float qn = rsqrtf(qo[0] * qo[0] + qo[1] * qo[1] + qo[2] * qo[2] + qo[3] * qo[3]);
#pragma unroll
    for (int i = 0; i < 4; i++) res[3 + i] = qo[i] * qn;
    {
        const u64 h2 = splat2(hdt);
#pragma unroll
        for (int p = 0; p < 3; p++) {
            u64 rp = f2fma(h2, f2add(vd1p[p], vd2p[p]), vp[p]);
            unpk2(rp, res[7 + 2 * p], res[8 + 2 * p]);
        }
    }

    __syncthreads();  // all reads of sx done before overwrite
    float* ox = &sx[tid * 13];
    if (active) {
#pragma unroll
        for (int i = 0; i < 13; i++) ox[i] = res[i];
    }
    __syncthreads();

    if (remx >= 256 * 13) {
        float4* o4 = (float4*)(out + (size_t)rbase * 13);
        const float4* sx4 = (const float4*)sx;
#pragma unroll
        for (int i = tid; i < 256 * 13 / 4; i += 256) o4[i] = sx4[i];
    } else {
        for (int i = tid; i < 256 * 13; i += 256)
            if (i < remx) out[rbase * 13 + i] = sx[i];
    }
}

extern "C" void kernel_launch(void* const* d_in, const int* in_sizes, int n_in,
                              void* d_out, int out_size) {
    const float* x          = (const float*)d_in[0];
    const float* u          = (const float*)d_in[1];
    const float* mass       = (const float*)d_in[2];
    const float* volume     = (const float*)d_in[3];
    const float* cog        = (const float*)d_in[4];
    const float* cob        = (const float*)d_in[5];
    const float* mTot       = (const float*)d_in[6];
    const float* linDamp    = (const float*)d_in[7];
    const float* linDampFow = (const float*)d_in[8];
    const float* quadDamp   = (const float*)d_in[9];

    const int K = in_sizes[0] / 13;

    // Device address of the constant-bank backing store (not an allocation).
    void* csym = nullptr;
    cudaGetSymbolAddress(&csym, c_consts);

    prep_kernel<<<1, 64>>>((float*)csym, mass, volume, cog, cob,
                           mTot, linDamp, linDampFow, quadDamp);

    // Secondary launch with programmatic dependent launch: its staging phase
    // overlaps prep; cudaGridDependencySynchronize() gates the constant reads.
    const int blocks = (K + 255) / 256;
    cudaLaunchConfig_t cfg = {};
    cfg.gridDim  = dim3(blocks, 1, 1);
    cfg.blockDim = dim3(256, 1, 1);
    cfg.dynamicSmemBytes = 0;
    cfg.stream = 0;
    cudaLaunchAttribute attrs[1];
    attrs[0].id = cudaLaunchAttributeProgrammaticStreamSerialization;
    attrs[0].val.programmaticStreamSerializationAllowed = 1;
    cfg.attrs = attrs;
    cfg.numAttrs = 1;
    cudaError_t err = cudaLaunchKernelEx(&cfg, auv_kernel,
                                         x, u, (float*)d_out, K);
    if (err != cudaSuccess) {
        // Fallback: plain serialized launch (identical semantics, no overlap)
        auv_kernel<<<blocks, 256>>>(x, u, (float*)d_out, K);
    }
}

// round 15
// speedup vs baseline: 1.0138x; 1.0138x over previous
#include <cuda_runtime.h>
#include <math.h>

#define KDT   0.1f
#define KG    9.81f
#define KRHO  1028.0f

typedef unsigned long long u64;

// Constant layout (floats). All 6x6 matrices COLUMN-MAJOR:
// c[base + j*6 + i] = M[i][j]  -> 64-bit pair loads of (M[2p][j], M[2p+1][j]).
// [0:36)    Minv
// [36:72)   mTot
// [72:108)  MiLD = Minv @ linDamp
// [108:144) linDampFow
// [144:150) quadDamp diagonal
// [150:168) negGm (6x3): -Minv@Ag, column-major
// [168]     lf-nonzero flag
#define NC 172
__constant__ __align__(16) float c_consts[NC];

// Parallel prep: 64 threads, one-element-per-thread Gauss-Jordan in shared.
// Writes derived constants DIRECTLY into the constant-bank backing store;
// the launch boundary invalidates constant caches before auv_kernel reads.
__global__ void prep_kernel(float* __restrict__ c_dst,
                            const float* mass, const float* volume,
                            const float* cog, const float* cob,
                            const float* mTot, const float* linDamp,
                            const float* linDampFow, const float* quadDamp) {
    __shared__ float As[36], Bs[36], MiLD[36], Ag[18], fv[6];
    __shared__ int piv_s;

    const int t = threadIdx.x;
    const int r = t / 6, c = t % 6;   // element (r,c) for t < 36

    if (t < 36) { As[t] = mTot[t]; Bs[t] = (r == c) ? 1.0f : 0.0f; }
    __syncthreads();

    for (int k = 0; k < 6; k++) {
        if (t == 0) {
            int piv = k; float best = fabsf(As[k * 6 + k]);
            for (int rr = k + 1; rr < 6; rr++) {
                float a = fabsf(As[rr * 6 + k]);
                if (a > best) { best = a; piv = rr; }
            }
            piv_s = piv;
        }
        __syncthreads();
        const int piv = piv_s;
        if (piv != k && t < 6) {
            float tmp = As[k * 6 + t]; As[k * 6 + t] = As[piv * 6 + t]; As[piv * 6 + t] = tmp;
            tmp = Bs[k * 6 + t]; Bs[k * 6 + t] = Bs[piv * 6 + t]; Bs[piv * 6 + t] = tmp;
        }
        __syncthreads();
        const float inv = 1.0f / As[k * 6 + k];
        if (t < 6) { As[k * 6 + t] *= inv; Bs[k * 6 + t] *= inv; }
        __syncthreads();
        if (t < 6) fv[t] = As[t * 6 + k];
        __syncthreads();
        if (t < 36 && r != k) {
            const float f = fv[r];
            As[t] -= f * As[k * 6 + c];
            Bs[t] -= f * Bs[k * 6 + c];
        }
        __syncthreads();
    }
    // Bs = Minv (row-major)

    if (t < 36) {
        float acc = 0.0f;
        for (int kk = 0; kk < 6; kk++) acc += Bs[r * 6 + kk] * linDamp[kk * 6 + c];
        MiLD[t] = acc;
    }

    if (t == 0) {
        const float fgz = -mass[0] * KG;
        const float fbz = volume[0] * KRHO * KG;
        for (int ii = 0; ii < 18; ii++) Ag[ii] = 0.0f;
        Ag[0 * 3 + 0] = Ag[1 * 3 + 1] = Ag[2 * 3 + 2] = -(fgz + fbz);
        const float cg0 = cog[0], cg1 = cog[1], cg2 = cog[2];
        const float cb0 = cob[0], cb1 = cob[1], cb2 = cob[2];
        Ag[3 * 3 + 1] = -(-fgz * cg2 - fbz * cb2);
        Ag[3 * 3 + 2] = -( fgz * cg1 + fbz * cb1);
        Ag[4 * 3 + 0] = -( fgz * cg2 + fbz * cb2);
        Ag[4 * 3 + 2] = -(-fgz * cg0 - fbz * cb0);
        Ag[5 * 3 + 0] = -(-fgz * cg1 - fbz * cb1);
        Ag[5 * 3 + 1] = -( fgz * cg0 + fbz * cb0);
    }
    __syncthreads();

    if (t < 36) {
        const int j = t / 6, i = t % 6;
        c_dst[0   + t] = Bs[i * 6 + j];
        c_dst[36  + t] = mTot[i * 6 + j];
        c_dst[72  + t] = MiLD[i * 6 + j];
        c_dst[108 + t] = linDampFow[i * 6 + j];
    }
    if (t < 6) c_dst[144 + t] = quadDamp[t * 7];
    if (t < 18) {
        const int jj = t / 6, i = t % 6;
        float acc = 0.0f;
        for (int kk = 0; kk < 6; kk++) acc += Bs[i * 6 + kk] * Ag[kk * 3 + jj];
        c_dst[150 + jj * 6 + i] = -acc;
    }
    if (t == 32) {
        float nz = 0.0f;
        for (int ii = 0; ii < 36; ii++)
            if (linDampFow[ii] != 0.0f) nz = 1.0f;
        c_dst[168] = nz;
    }
}

// ---------------- packed f32x2 helpers ----------------
__device__ __forceinline__ u64 pk2(float lo, float hi) {
    u64 r; asm("mov.b64 %0,{%1,%2};" : "=l"(r) : "f"(lo), "f"(hi)); return r;
}
__device__ __forceinline__ u64 splat2(float a) {
    u64 r; asm("mov.b64 %0,{%1,%1};" : "=l"(r) : "f"(a)); return r;
}
__device__ __forceinline__ void unpk2(u64 p, float& lo, float& hi) {
    asm("mov.b64 {%0,%1},%2;" : "=f"(lo), "=f"(hi) : "l"(p));
}
__device__ __forceinline__ u64 f2fma(u64 a, u64 b, u64 c) {
    u64 d; asm("fma.rn.f32x2 %0,%1,%2,%3;" : "=l"(d) : "l"(a), "l"(b), "l"(c)); return d;
}
__device__ __forceinline__ u64 f2mul(u64 a, u64 b) {
    u64 d; asm("mul.rn.f32x2 %0,%1,%2;" : "=l"(d) : "l"(a), "l"(b)); return d;
}
__device__ __forceinline__ u64 f2add(u64 a, u64 b) {
    u64 d; asm("add.rn.f32x2 %0,%1,%2;" : "=l"(d) : "l"(a), "l"(b)); return d;
}
// 64-bit constant-bank fetch of a column pair (uniform address -> LDCU/UR path)
#define C2(base, j, p) (*reinterpret_cast<const u64*>(&c_consts[(base) + (j) * 6 + (p) * 2]))

// One RK stage. q,v scalar; sv = splats of v; Uvp = packed Minv@u.
__device__ __forceinline__ void fossen_stage(const float q[4], const float v[6],
                                             const u64 sv[6], const u64 Uvp[3],
                                             float pd[7], u64 vdp[3]) {
    const float qx = q[0], qy = q[1], qz = q[2], qw = q[3];

    const float r00 = 1.0f - 2.0f * (qy * qy + qz * qz);
    const float r01 = 2.0f * (qx * qy - qz * qw);
    const float r02 = 2.0f * (qx * qz + qy * qw);
    const float r10 = 2.0f * (qx * qy + qz * qw);
    const float r11 = 1.0f - 2.0f * (qx * qx + qz * qz);
    const float r12 = 2.0f * (qy * qz - qx * qw);
    const float r20 = 2.0f * (qx * qz - qy * qw);
    const float r21 = 2.0f * (qy * qz + qx * qw);
    const float r22 = 1.0f - 2.0f * (qx * qx + qy * qy);

    const float v0 = v[0], v1 = v[1], v2 = v[2];
    const float w0 = v[3], w1 = v[4], w2 = v[5];

    pd[0] = r00 * v0 + r01 * v1 + r02 * v2;
    pd[1] = r10 * v0 + r11 * v1 + r12 * v2;
    pd[2] = r20 * v0 + r21 * v1 + r22 * v2;
    pd[3] = 0.5f * (-qx * w0 - qy * w1 - qz * w2);
    pd[4] = 0.5f * ( qw * w0 - qz * w1 + qy * w2);
    pd[5] = 0.5f * ( qz * w0 + qw * w1 - qx * w2);
    pd[6] = 0.5f * (-qy * w0 + qx * w1 + qw * w2);

    // mv = mTot @ v  (packed, column-major accumulate)
    u64 mvp[3];
#pragma unroll
    for (int p = 0; p < 3; p++) mvp[p] = f2mul(C2(36, 0, p), sv[0]);
#pragma unroll
    for (int j = 1; j < 6; j++)
#pragma unroll
        for (int p = 0; p < 3; p++) mvp[p] = f2fma(C2(36, j, p), sv[j], mvp[p]);
    float mv0, mv1, mv2, mv3, mv4, mv5;
    unpk2(mvp[0], mv0, mv1); unpk2(mvp[1], mv2, mv3); unpk2(mvp[2], mv4, mv5);

    // s = quad|v|v - Cv  (scalar)
    float s[6];
    s[0] = c_consts[144] * fabsf(v0) * v0 + (mv1 * w2 - mv2 * w1);
    s[1] = c_consts[145] * fabsf(v1) * v1 + (mv2 * w0 - mv0 * w2);
    s[2] = c_consts[146] * fabsf(v2) * v2 + (mv0 * w1 - mv1 * w0);
    s[3] = c_consts[147] * fabsf(w0) * w0 + (mv1 * v2 - mv2 * v1) + (mv4 * w2 - mv5 * w1);
    s[4] = c_consts[148] * fabsf(w1) * w1 + (mv2 * v0 - mv0 * v2) + (mv5 * w0 - mv3 * w2);
    s[5] = c_consts[149] * fabsf(w2) * w2 + (mv0 * v1 - mv1 * v0) + (mv3 * w1 - mv4 * w0);

    // optional linDampFow term: s_i += v_i * (lf_i . v)
    if (c_consts[168] != 0.0f) {
        u64 dp[3];
#pragma unroll
        for (int p = 0; p < 3; p++) dp[p] = f2mul(C2(108, 0, p), sv[0]);
#pragma unroll
        for (int j = 1; j < 6; j++)
#pragma unroll
            for (int p = 0; p < 3; p++) dp[p] = f2fma(C2(108, j, p), sv[j], dp[p]);
        float d0, d1, d2, d3, d4, d5;
        unpk2(dp[0], d0, d1); unpk2(dp[1], d2, d3); unpk2(dp[2], d4, d5);
        s[0] += v0 * d0; s[1] += v1 * d1; s[2] += v2 * d2;
        s[3] += w0 * d3; s[4] += w1 * d4; s[5] += w2 * d5;
    }

    // vd = Uv + MiLD@v + Minv@s + negGm@r2   (packed)
    u64 acc[3] = { Uvp[0], Uvp[1], Uvp[2] };
#pragma unroll
    for (int j = 0; j < 6; j++) {
#pragma unroll
        for (int p = 0; p < 3; p++) acc[p] = f2fma(C2(72, j, p), sv[j], acc[p]);
    }
#pragma unroll
    for (int j = 0; j < 6; j++) {
        const u64 ssj = splat2(s[j]);
#pragma unroll
        for (int p = 0; p < 3; p++) acc[p] = f2fma(C2(0, j, p), ssj, acc[p]);
    }
    const u64 sr0 = splat2(r20), sr1 = splat2(r21), sr2 = splat2(r22);
#pragma unroll
    for (int p = 0; p < 3; p++) {
        acc[p] = f2fma(C2(150, 0, p), sr0, acc[p]);
        acc[p] = f2fma(C2(150, 1, p), sr1, acc[p]);
        acc[p] = f2fma(C2(150, 2, p), sr2, acc[p]);
    }
    vdp[0] = acc[0]; vdp[1] = acc[1]; vdp[2] = acc[2];
}

// Full RK2 for one row: reads state from mx (13 floats) and control from uu
// (6 floats); writes the 13-float result back to mx.
__device__ __forceinline__ void rk2_row(float* mx, const float* uu) {
    float q[4], v[6];
#pragma unroll
    for (int i = 0; i < 4; i++) q[i] = mx[3 + i];
#pragma unroll
    for (int i = 0; i < 6; i++) v[i] = mx[7 + i];

    // Uv = Minv @ u
    u64 Uvp[3];
    {
        u64 s0 = splat2(uu[0]);
#pragma unroll
        for (int p = 0; p < 3; p++) Uvp[p] = f2mul(C2(0, 0, p), s0);
#pragma unroll
        for (int j = 1; j < 6; j++) {
            const u64 sj = splat2(uu[j]);
#pragma unroll
            for (int p = 0; p < 3; p++) Uvp[p] = f2fma(C2(0, j, p), sj, Uvp[p]);
        }
    }

    // Stage 1
    u64 sv1[6];
#pragma unroll
    for (int j = 0; j < 6; j++) sv1[j] = splat2(v[j]);
    float pd1[7]; u64 vd1p[3];
    fossen_stage(q, v, sv1, Uvp, pd1, vd1p);

    // Midpoint
    const u64 dt2 = splat2(KDT);
    u64 vp[3] = { pk2(v[0], v[1]), pk2(v[2], v[3]), pk2(v[4], v[5]) };
    float q2[4], v2[6];
#pragma unroll
    for (int i = 0; i < 4; i++) q2[i] = q[i] + KDT * pd1[3 + i];
    {
        u64 v2p[3];
#pragma unroll
        for (int p = 0; p < 3; p++) v2p[p] = f2fma(dt2, vd1p[p], vp[p]);
        unpk2(v2p[0], v2[0], v2[1]); unpk2(v2p[1], v2[2], v2[3]); unpk2(v2p[2], v2[4], v2[5]);
    }

    // Stage 2
    u64 sv2[6];
#pragma unroll
    for (int j = 0; j < 6; j++) sv2[j] = splat2(v2[j]);
    float pd2[7]; u64 vd2p[3];
    fossen_stage(q2, v2, sv2, Uvp, pd2, vd2p);

    // Combine + quaternion normalize; write back into mx
    const float hdt = 0.5f * KDT;
#pragma unroll
    for (int i = 0; i < 3; i++) mx[i] = mx[i] + hdt * (pd1[i] + pd2[i]);
    float qo[4];
#pragma unroll
    for (int i = 0; i < 4; i++) qo[i] = q[i] + hdt * (pd1[3 + i] + pd2[3 + i]);
    const float qn = rsqrtf(qo[0] * qo[0] + qo[1] * qo[1] + qo[2] * qo[2] + qo[3] * qo[3]);
#pragma unroll
    for (int i = 0; i < 4; i++) mx[3 + i] = qo[i] * qn;
    {
        const u64 h2 = splat2(hdt);
#pragma unroll
        for (int p = 0; p < 3; p++) {
            u64 rp = f2fma(h2, f2add(vd1p[p], vd2p[p]), vp[p]);
            unpk2(rp, mx[7 + 2 * p], mx[8 + 2 * p]);
        }
    }
}

// 128 threads, 2 rows/thread (rows tid and tid+128 of a 256-row tile):
// two independent dependency chains per thread -> ~2x ILP vs 1 row/thread.
__global__ __launch_bounds__(128) void auv_kernel(const float* __restrict__ x,
                                                  const float* __restrict__ u,
                                                  float* __restrict__ out, int K) {
    __shared__ float sx[256 * 13];
    __shared__ float su[256 * 6];

    const int tid = threadIdx.x;
    const int rbase = blockIdx.x * 256;
    const int total_x = K * 13;
    const int total_u = K * 6;
    const int remx = total_x - rbase * 13;
    const int remu = total_u - rbase * 6;

    // Coalesced staging (128 threads over the 256-row tile)
    if (remx >= 256 * 13 && remu >= 256 * 6) {
        const float4* x4 = (const float4*)(x + (size_t)rbase * 13);
        float4* sx4 = (float4*)sx;
#pragma unroll
        for (int i = tid; i < 256 * 13 / 4; i += 128) sx4[i] = x4[i];
        const float4* u4 = (const float4*)(u + (size_t)rbase * 6);
        float4* su4 = (float4*)su;
#pragma unroll
        for (int i = tid; i < 256 * 6 / 4; i += 128) su4[i] = u4[i];
    } else {
        for (int i = tid; i < 256 * 13; i += 128)
            sx[i] = (i < remx) ? x[rbase * 13 + i] : 0.0f;
        for (int i = tid; i < 256 * 6; i += 128)
            su[i] = (i < remu) ? u[rbase * 6 + i] : 0.0f;
    }
    __syncthreads();

    // Two independent rows per thread; unrolled so ptxas interleaves the chains.
    // Each (thread, rr) owns a distinct row: in-place sx update, no cross-thread
    // hazard (every thread reads/writes only its own rows' 13-float slices).
#pragma unroll
    for (int rr = 0; rr < 2; rr++) {
        const int lr = tid + rr * 128;
        if (rbase + lr < K) {
            rk2_row(&sx[lr * 13], &su[lr * 6]);
        }
    }
    __syncthreads();

    // Coalesced writeback
    if (remx >= 256 * 13) {
        float4* o4 = (float4*)(out + (size_t)rbase * 13);
        const float4* sx4 = (const float4*)sx;
#pragma unroll
        for (int i = tid; i < 256 * 13 / 4; i += 128) o4[i] = sx4[i];
    } else {
        for (int i = tid; i < 256 * 13; i += 128)
            if (i < remx) out[rbase * 13 + i] = sx[i];
    }
}

extern "C" void kernel_launch(void* const* d_in, const int* in_sizes, int n_in,
                              void* d_out, int out_size) {
    const float* x          = (const float*)d_in[0];
    const float* u          = (const float*)d_in[1];
    const float* mass       = (const float*)d_in[2];
    const float* volume     = (const float*)d_in[3];
    const float* cog        = (const float*)d_in[4];
    const float* cob        = (const float*)d_in[5];
    const float* mTot       = (const float*)d_in[6];
    const float* linDamp    = (const float*)d_in[7];
    const float* linDampFow = (const float*)d_in[8];
    const float* quadDamp   = (const float*)d_in[9];

    const int K = in_sizes[0] / 13;

    // Device address of the constant-bank backing store (not an allocation).
    void* csym = nullptr;
    cudaGetSymbolAddress(&csym, c_consts);

    prep_kernel<<<1, 64>>>((float*)csym, mass, volume, cog, cob,
                           mTot, linDamp, linDampFow, quadDamp);

    const int blocks = (K + 255) / 256;
    auv_kernel<<<blocks, 128>>>(x, u, (float*)d_out, K);
}